// round 1
// baseline (speedup 1.0000x reference)
#include <cuda_runtime.h>

#define Nn 50000
#define Ee 800000
#define Gg 2048
#define Hh 128

// ---------------- device scratch (static: no allocations allowed) ----------
__device__ float g_Pa[Nn * Hh];    // nf @ e_w1[0:128]
__device__ float g_Pb[Nn * Hh];    // nf @ e_w1[128:256]
__device__ float g_Qb[Gg * Hh];    // lat @ e_w1[256:262] + e_b1
__device__ float g_agg[Nn * Hh];   // scatter-sum accumulator
__device__ int   g_cnt[Nn];        // per-node edge count

__device__ __forceinline__ float silu_f(float x) {
    return x / (1.0f + __expf(-x));
}

// ---------------------------------------------------------------------------
// Kernel 1: Pa/Pb precompute + zero agg/cnt.  32 rows x 256 cols per block.
// ---------------------------------------------------------------------------
__launch_bounds__(256)
__global__ void prep_node_kernel(const float* __restrict__ nf,
                                 const float* __restrict__ e_w1)
{
    __shared__ float nfs[32 * 128];   // 16 KB
    __shared__ float wks[16 * 256];   // 16 KB

    const int tid  = threadIdx.x;
    const int row0 = blockIdx.x * 32;

    for (int idx = tid; idx < 32 * 128; idx += 256) {
        int r = idx >> 7, c = idx & 127;
        int row = row0 + r;
        nfs[idx] = (row < Nn) ? nf[row * 128 + c] : 0.0f;
        if (row < Nn) g_agg[row * 128 + c] = 0.0f;
    }
    if (tid < 32 && row0 + tid < Nn) g_cnt[row0 + tid] = 0;

    const int ty = tid >> 5;   // 0..7  -> rows ty*4 .. ty*4+3
    const int tx = tid & 31;   // 0..31 -> cols tx*8 .. tx*8+7 (of 256)

    float acc[4][8];
#pragma unroll
    for (int i = 0; i < 4; i++)
#pragma unroll
        for (int j = 0; j < 8; j++) acc[i][j] = 0.0f;

    for (int kt = 0; kt < 128; kt += 16) {
        __syncthreads();
        for (int idx = tid; idx < 16 * 256; idx += 256) {
            int kl = idx >> 8, c = idx & 255;
            int k = kt + kl;
            wks[idx] = (c < 128) ? e_w1[k * 128 + c]
                                 : e_w1[(128 + k) * 128 + (c - 128)];
        }
        __syncthreads();
#pragma unroll
        for (int kl = 0; kl < 16; kl++) {
            float a0 = nfs[(ty * 4 + 0) * 128 + kt + kl];
            float a1 = nfs[(ty * 4 + 1) * 128 + kt + kl];
            float a2 = nfs[(ty * 4 + 2) * 128 + kt + kl];
            float a3 = nfs[(ty * 4 + 3) * 128 + kt + kl];
            const float4 bA = *(const float4*)&wks[kl * 256 + tx * 8];
            const float4 bB = *(const float4*)&wks[kl * 256 + tx * 8 + 4];
            float bb[8] = {bA.x, bA.y, bA.z, bA.w, bB.x, bB.y, bB.z, bB.w};
#pragma unroll
            for (int j = 0; j < 8; j++) {
                acc[0][j] += a0 * bb[j];
                acc[1][j] += a1 * bb[j];
                acc[2][j] += a2 * bb[j];
                acc[3][j] += a3 * bb[j];
            }
        }
    }

#pragma unroll
    for (int i = 0; i < 4; i++) {
        int row = row0 + ty * 4 + i;
        if (row >= Nn) continue;
#pragma unroll
        for (int j = 0; j < 8; j++) {
            int col = tx * 8 + j;
            if (col < 128) g_Pa[row * 128 + col] = acc[i][j];
            else           g_Pb[row * 128 + (col - 128)] = acc[i][j];
        }
    }
}

// ---------------------------------------------------------------------------
// Kernel 2: per-graph lattice term + edge bias 1.
// ---------------------------------------------------------------------------
__global__ void prep_graph_kernel(const float* __restrict__ lat,
                                  const float* __restrict__ e_w1,
                                  const float* __restrict__ e_b1)
{
    const int g = blockIdx.x;
    const int c = threadIdx.x;
    float acc = e_b1[c];
#pragma unroll
    for (int k = 0; k < 6; k++)
        acc += lat[g * 6 + k] * e_w1[(256 + k) * 128 + c];
    g_Qb[g * 128 + c] = acc;
}

// ---------------------------------------------------------------------------
// Kernel 3: fused edge pipeline (persistent).
//   e1 = silu(Pa[src] + Pb[dst] + Qb[g] + fd@W1d)      (Phase A)
//   ef = silu(e1 @ W2 + b2)                            (Phase B, SIMT GEMM)
//   atomicAdd into g_agg[src], count into g_cnt.
// 64 edges per tile, 256 threads. ~100.5 KB dyn smem, 2 CTAs/SM.
// ---------------------------------------------------------------------------
#define EDGE_SMEM_FLOATS (16384 + 64 * 132 + 384 + 128 + 192 + 192)
#define EDGE_SMEM_BYTES  (EDGE_SMEM_FLOATS * 4)

__launch_bounds__(256, 2)
__global__ void edge_kernel(const float* __restrict__ frac_diff,
                            const int*   __restrict__ ei,
                            const int*   __restrict__ e2g,
                            const float* __restrict__ e_w1,
                            const float* __restrict__ e_w2,
                            const float* __restrict__ e_b2)
{
    extern __shared__ float sm[];
    float* W2s  = sm;                    // 128x128            = 16384
    float* E1s  = sm + 16384;            // 64 x 132 (padded)  =  8448
    float* w1ds = sm + 16384 + 8448;     // 3 x 128            =   384
    float* b2s  = w1ds + 384;            // 128
    float* fds  = b2s + 128;             // 192
    int*   srcs = (int*)(fds + 192);     // 64
    int*   dsts = srcs + 64;             // 64
    int*   gs   = srcs + 128;            // 64

    const int tid = threadIdx.x;

    for (int idx = tid; idx < 16384; idx += 256) W2s[idx] = e_w2[idx];
    for (int idx = tid; idx < 384; idx += 256)   w1ds[idx] = e_w1[262 * 128 + idx];
    if (tid < 128) b2s[tid] = e_b2[tid];

    const int ty = tid >> 4;   // 0..15 -> rows ty*4 .. ty*4+3
    const int tx = tid & 15;   // 0..15 -> cols tx*8 .. tx*8+7

    const int ntiles = Ee / 64;   // 12500
    for (int tile = blockIdx.x; tile < ntiles; tile += gridDim.x) {
        __syncthreads();   // previous tile's Phase B done before smem reuse
        const int e0 = tile * 64;
        if (tid < 64) {
            int e = e0 + tid;
            int s = ei[e];
            srcs[tid] = s;
            dsts[tid] = ei[Ee + e];
            gs[tid]   = e2g[e];
            atomicAdd(&g_cnt[s], 1);
        } else if (tid < 256) {
            int idx = tid - 64;
            if (idx < 192) fds[idx] = frac_diff[e0 * 3 + idx];
        }
        __syncthreads();

        // Phase A: build e1 tile (gathers hit L2: Pa/Pb/Qb resident)
#pragma unroll 4
        for (int idx = tid; idx < 64 * 128; idx += 256) {
            int r = idx >> 7, c = idx & 127;
            float v = g_Pa[srcs[r] * 128 + c]
                    + g_Pb[dsts[r] * 128 + c]
                    + g_Qb[gs[r]   * 128 + c]
                    + fds[r * 3 + 0] * w1ds[c]
                    + fds[r * 3 + 1] * w1ds[128 + c]
                    + fds[r * 3 + 2] * w1ds[256 + c];
            E1s[r * 132 + c] = silu_f(v);
        }
        __syncthreads();

        // Phase B: [64,128] @ [128,128]
        float acc[4][8];
#pragma unroll
        for (int i = 0; i < 4; i++)
#pragma unroll
            for (int j = 0; j < 8; j++) acc[i][j] = 0.0f;

        const float* a0p = E1s + (ty * 4) * 132;
#pragma unroll 8
        for (int k = 0; k < 128; k++) {
            float a0 = a0p[k];
            float a1 = a0p[132 + k];
            float a2 = a0p[264 + k];
            float a3 = a0p[396 + k];
            const float4 bA = *(const float4*)&W2s[k * 128 + tx * 8];
            const float4 bB = *(const float4*)&W2s[k * 128 + tx * 8 + 4];
            float bb[8] = {bA.x, bA.y, bA.z, bA.w, bB.x, bB.y, bB.z, bB.w};
#pragma unroll
            for (int j = 0; j < 8; j++) {
                acc[0][j] += a0 * bb[j];
                acc[1][j] += a1 * bb[j];
                acc[2][j] += a2 * bb[j];
                acc[3][j] += a3 * bb[j];
            }
        }

        float bj[8];
#pragma unroll
        for (int j = 0; j < 8; j++) bj[j] = b2s[tx * 8 + j];
#pragma unroll
        for (int i = 0; i < 4; i++) {
            int node = srcs[ty * 4 + i];
            float* dst = g_agg + node * 128 + tx * 8;
#pragma unroll
            for (int j = 0; j < 8; j++)
                atomicAdd(dst + j, silu_f(acc[i][j] + bj[j]));
        }
    }
}

// ---------------------------------------------------------------------------
// Kernel 4: node model + residual.  32 rows per block.
//   h  = silu([nf | agg/cnt] @ n_w1 + n_b1)
//   out= nf + silu(h @ n_w2 + n_b2)
// ---------------------------------------------------------------------------
#define XS_STRIDE 260
#define H1_STRIDE 132
#define NODE_SMEM_FLOATS (32 * XS_STRIDE + 32 * H1_STRIDE + 32 * 128 + 128 + 128 + 32)
#define NODE_SMEM_BYTES  (NODE_SMEM_FLOATS * 4)

__launch_bounds__(256)
__global__ void node_out_kernel(const float* __restrict__ nf,
                                const float* __restrict__ n_w1,
                                const float* __restrict__ n_b1,
                                const float* __restrict__ n_w2,
                                const float* __restrict__ n_b2,
                                float* __restrict__ out)
{
    extern __shared__ float sm[];
    float* xs   = sm;                                  // 32 x 260
    float* h1s  = sm + 32 * XS_STRIDE;                 // 32 x 132
    float* wks  = h1s + 32 * H1_STRIDE;                // 32 x 128
    float* b1s  = wks + 32 * 128;                      // 128
    float* b2s  = b1s + 128;                           // 128
    float* cinv = b2s + 128;                           // 32

    const int tid  = threadIdx.x;
    const int row0 = blockIdx.x * 32;

    if (tid < 128) { b1s[tid] = n_b1[tid]; b2s[tid] = n_b2[tid]; }
    if (tid < 32) {
        int row = row0 + tid;
        cinv[tid] = (row < Nn) ? 1.0f / fmaxf((float)g_cnt[row], 1.0f) : 0.0f;
    }
    __syncthreads();

    for (int idx = tid; idx < 32 * 256; idx += 256) {
        int r = idx >> 8, c = idx & 255;
        int row = row0 + r;
        float v = 0.0f;
        if (row < Nn)
            v = (c < 128) ? nf[row * 128 + c]
                          : g_agg[row * 128 + (c - 128)] * cinv[r];
        xs[r * XS_STRIDE + c] = v;
    }

    const int ty = tid >> 4;   // 0..15 -> rows ty*2, ty*2+1
    const int tx = tid & 15;   // cols tx*8..tx*8+7

    // GEMM1: [32,256] @ [256,128]
    float acc[2][8];
#pragma unroll
    for (int i = 0; i < 2; i++)
#pragma unroll
        for (int j = 0; j < 8; j++) acc[i][j] = 0.0f;

    for (int kt = 0; kt < 256; kt += 32) {
        __syncthreads();
        for (int idx = tid; idx < 32 * 128; idx += 256) {
            int kl = idx >> 7, c = idx & 127;
            wks[idx] = n_w1[(kt + kl) * 128 + c];
        }
        __syncthreads();
#pragma unroll
        for (int kl = 0; kl < 32; kl++) {
            float a0 = xs[(ty * 2 + 0) * XS_STRIDE + kt + kl];
            float a1 = xs[(ty * 2 + 1) * XS_STRIDE + kt + kl];
            const float4 bA = *(const float4*)&wks[kl * 128 + tx * 8];
            const float4 bB = *(const float4*)&wks[kl * 128 + tx * 8 + 4];
            float bb[8] = {bA.x, bA.y, bA.z, bA.w, bB.x, bB.y, bB.z, bB.w};
#pragma unroll
            for (int j = 0; j < 8; j++) {
                acc[0][j] += a0 * bb[j];
                acc[1][j] += a1 * bb[j];
            }
        }
    }
    __syncthreads();
#pragma unroll
    for (int i = 0; i < 2; i++)
#pragma unroll
        for (int j = 0; j < 8; j++) {
            int c = tx * 8 + j;
            h1s[(ty * 2 + i) * H1_STRIDE + c] = silu_f(acc[i][j] + b1s[c]);
        }
    __syncthreads();

    // GEMM2: [32,128] @ [128,128]
    float acc2[2][8];
#pragma unroll
    for (int i = 0; i < 2; i++)
#pragma unroll
        for (int j = 0; j < 8; j++) acc2[i][j] = 0.0f;

    for (int kt = 0; kt < 128; kt += 32) {
        __syncthreads();
        for (int idx = tid; idx < 32 * 128; idx += 256) {
            int kl = idx >> 7, c = idx & 127;
            wks[idx] = n_w2[(kt + kl) * 128 + c];
        }
        __syncthreads();
#pragma unroll
        for (int kl = 0; kl < 32; kl++) {
            float a0 = h1s[(ty * 2 + 0) * H1_STRIDE + kt + kl];
            float a1 = h1s[(ty * 2 + 1) * H1_STRIDE + kt + kl];
            const float4 bA = *(const float4*)&wks[kl * 128 + tx * 8];
            const float4 bB = *(const float4*)&wks[kl * 128 + tx * 8 + 4];
            float bb[8] = {bA.x, bA.y, bA.z, bA.w, bB.x, bB.y, bB.z, bB.w};
#pragma unroll
            for (int j = 0; j < 8; j++) {
                acc2[0][j] += a0 * bb[j];
                acc2[1][j] += a1 * bb[j];
            }
        }
    }

#pragma unroll
    for (int i = 0; i < 2; i++) {
        int row = row0 + ty * 2 + i;
        if (row >= Nn) continue;
#pragma unroll
        for (int j = 0; j < 8; j++) {
            int c = tx * 8 + j;
            out[row * 128 + c] = nf[row * 128 + c] + silu_f(acc2[i][j] + b2s[c]);
        }
    }
}

// ---------------------------------------------------------------------------
extern "C" void kernel_launch(void* const* d_in, const int* in_sizes, int n_in,
                              void* d_out, int out_size)
{
    (void)in_sizes; (void)n_in; (void)out_size;
    const float* nf   = (const float*)d_in[0];
    // d_in[1] = frac_coords (unused by reference)
    const float* lat  = (const float*)d_in[2];
    const float* fd   = (const float*)d_in[3];
    const int*   ei   = (const int*)d_in[4];
    const int*   e2g  = (const int*)d_in[5];
    const float* e_w1 = (const float*)d_in[6];
    const float* e_b1 = (const float*)d_in[7];
    const float* e_w2 = (const float*)d_in[8];
    const float* e_b2 = (const float*)d_in[9];
    const float* n_w1 = (const float*)d_in[10];
    const float* n_b1 = (const float*)d_in[11];
    const float* n_w2 = (const float*)d_in[12];
    const float* n_b2 = (const float*)d_in[13];
    float* out = (float*)d_out;

    cudaFuncSetAttribute(edge_kernel,
                         cudaFuncAttributeMaxDynamicSharedMemorySize,
                         EDGE_SMEM_BYTES);
    cudaFuncSetAttribute(node_out_kernel,
                         cudaFuncAttributeMaxDynamicSharedMemorySize,
                         NODE_SMEM_BYTES);

    prep_node_kernel<<<(Nn + 31) / 32, 256>>>(nf, e_w1);
    prep_graph_kernel<<<Gg, 128>>>(lat, e_w1, e_b1);
    edge_kernel<<<304, 256, EDGE_SMEM_BYTES>>>(fd, ei, e2g, e_w1, e_w2, e_b2);
    node_out_kernel<<<(Nn + 31) / 32, 256, NODE_SMEM_BYTES>>>(
        nf, n_w1, n_b1, n_w2, n_b2, out);
}

// round 4
// speedup vs baseline: 1.2302x; 1.2302x over previous
#include <cuda_runtime.h>
#include <cuda_bf16.h>
#include <cstdint>

#define Nn 50000
#define Ee 800000
#define Gg 2048
#define Hh 128

// single dynamic-smem symbol shared by all kernels (cast per kernel)
extern __shared__ char dyn_smem[];

// ---------------- device scratch ----------
__device__ float g_Pa[Nn * Hh];    // nf @ e_w1[0:128]
__device__ float g_Pb[Nn * Hh];    // nf @ e_w1[128:256]
__device__ float g_Qb[Gg * Hh];    // lat @ e_w1[256:262] + e_b1
__device__ float g_agg[Nn * Hh];   // scatter-sum accumulator
__device__ int   g_cnt[Nn];        // per-node edge count

__device__ __forceinline__ float silu_f(float x) {
    return x / (1.0f + __expf(-x));
}

// bf16 hi/lo split of a pair -> packed bf16x2 (hi returned, lo via ref)
__device__ __forceinline__ uint32_t split_pack(float v0, float v1, uint32_t& lo) {
    __nv_bfloat16 h0 = __float2bfloat16_rn(v0);
    __nv_bfloat16 h1 = __float2bfloat16_rn(v1);
    float r0 = v0 - __bfloat162float(h0);
    float r1 = v1 - __bfloat162float(h1);
    __nv_bfloat16 l0 = __float2bfloat16_rn(r0);
    __nv_bfloat16 l1 = __float2bfloat16_rn(r1);
    lo = (uint32_t)__bfloat16_as_ushort(l0) | ((uint32_t)__bfloat16_as_ushort(l1) << 16);
    return (uint32_t)__bfloat16_as_ushort(h0) | ((uint32_t)__bfloat16_as_ushort(h1) << 16);
}

// warp-level bf16 MMA, fp32 accum (sm_80+, compiles at base sm_103 target)
__device__ __forceinline__ void mma16816(float* d, const uint32_t* a, const uint32_t* b) {
    asm volatile(
        "mma.sync.aligned.m16n8k16.row.col.f32.bf16.bf16.f32 "
        "{%0,%1,%2,%3}, {%4,%5,%6,%7}, {%8,%9}, {%0,%1,%2,%3};"
        : "+f"(d[0]), "+f"(d[1]), "+f"(d[2]), "+f"(d[3])
        : "r"(a[0]), "r"(a[1]), "r"(a[2]), "r"(a[3]), "r"(b[0]), "r"(b[1]));
}

// vectorized f32x2 global reduction (PTX ISA 8.1+, sm_90+)
__device__ __forceinline__ void red_add_v2(float* p, float a, float b) {
    asm volatile("red.global.add.v2.f32 [%0], {%1, %2};"
                 :: "l"(p), "f"(a), "f"(b) : "memory");
}

// ---------------------------------------------------------------------------
// Kernel 1: Pa/Pb precompute + zero agg/cnt.  32 rows x 256 cols per block.
// ---------------------------------------------------------------------------
__launch_bounds__(256)
__global__ void prep_node_kernel(const float* __restrict__ nf,
                                 const float* __restrict__ e_w1)
{
    __shared__ float nfs[32 * 128];
    __shared__ float wks[16 * 256];

    const int tid  = threadIdx.x;
    const int row0 = blockIdx.x * 32;

    for (int idx = tid; idx < 32 * 128; idx += 256) {
        int r = idx >> 7, c = idx & 127;
        int row = row0 + r;
        nfs[idx] = (row < Nn) ? nf[row * 128 + c] : 0.0f;
        if (row < Nn) g_agg[row * 128 + c] = 0.0f;
    }
    if (tid < 32 && row0 + tid < Nn) g_cnt[row0 + tid] = 0;

    const int ty = tid >> 5;
    const int tx = tid & 31;

    float acc[4][8];
#pragma unroll
    for (int i = 0; i < 4; i++)
#pragma unroll
        for (int j = 0; j < 8; j++) acc[i][j] = 0.0f;

    for (int kt = 0; kt < 128; kt += 16) {
        __syncthreads();
        for (int idx = tid; idx < 16 * 256; idx += 256) {
            int kl = idx >> 8, c = idx & 255;
            int k = kt + kl;
            wks[idx] = (c < 128) ? e_w1[k * 128 + c]
                                 : e_w1[(128 + k) * 128 + (c - 128)];
        }
        __syncthreads();
#pragma unroll
        for (int kl = 0; kl < 16; kl++) {
            float a0 = nfs[(ty * 4 + 0) * 128 + kt + kl];
            float a1 = nfs[(ty * 4 + 1) * 128 + kt + kl];
            float a2 = nfs[(ty * 4 + 2) * 128 + kt + kl];
            float a3 = nfs[(ty * 4 + 3) * 128 + kt + kl];
            const float4 bA = *(const float4*)&wks[kl * 256 + tx * 8];
            const float4 bB = *(const float4*)&wks[kl * 256 + tx * 8 + 4];
            float bb[8] = {bA.x, bA.y, bA.z, bA.w, bB.x, bB.y, bB.z, bB.w};
#pragma unroll
            for (int j = 0; j < 8; j++) {
                acc[0][j] += a0 * bb[j];
                acc[1][j] += a1 * bb[j];
                acc[2][j] += a2 * bb[j];
                acc[3][j] += a3 * bb[j];
            }
        }
    }

#pragma unroll
    for (int i = 0; i < 4; i++) {
        int row = row0 + ty * 4 + i;
        if (row >= Nn) continue;
#pragma unroll
        for (int j = 0; j < 8; j++) {
            int col = tx * 8 + j;
            if (col < 128) g_Pa[row * 128 + col] = acc[i][j];
            else           g_Pb[row * 128 + (col - 128)] = acc[i][j];
        }
    }
}

// ---------------------------------------------------------------------------
// Kernel 2: per-graph lattice term + edge bias 1.
// ---------------------------------------------------------------------------
__global__ void prep_graph_kernel(const float* __restrict__ lat,
                                  const float* __restrict__ e_w1,
                                  const float* __restrict__ e_b1)
{
    const int g = blockIdx.x;
    const int c = threadIdx.x;
    float acc = e_b1[c];
#pragma unroll
    for (int k = 0; k < 6; k++)
        acc += lat[g * 6 + k] * e_w1[(256 + k) * 128 + c];
    g_Qb[g * 128 + c] = acc;
}

// ---------------------------------------------------------------------------
// Kernel 3: fused edge pipeline — mma.sync bf16 hi/lo (fp32-accurate) GEMM2.
//   Phase A: e1 = silu(Pa[src]+Pb[dst]+Qb[g]+fd@W1d) -> bf16 hi/lo SMEM planes
//   MMA:     D = Ah@Bh^T + Al@Bh^T + Ah@Bl^T    (B[n][k] = W2[k][n])
//   Epilog:  silu(D + b2) -> red.global.add.v2 into g_agg[src]
// 128 edges/tile, 256 threads (8 warps, 16 rows each), persistent grid=148.
// Planes are row-major, 136 bf16 row stride (68 words) -> conflict-free frags.
// ---------------------------------------------------------------------------
#define TILE_M 128
#define EDGE_NTILES (Ee / TILE_M)      // 6250
#define PLANE_WSTRIDE 68               // u32 words per row (136 bf16)
#define PLANE_WORDS   (128 * PLANE_WSTRIDE)   // 8704

// u32-granular smem offsets
#define O_SRC   0
#define O_DST   128
#define O_GS    256
#define O_FDS   384
#define O_B2    768
#define O_W1D   896
#define O_AHI   1280
#define O_ALO   (O_AHI + PLANE_WORDS)
#define O_BHI   (O_ALO + PLANE_WORDS)
#define O_BLO   (O_BHI + PLANE_WORDS)
#define EDGE_SMEM_BYTES ((O_BLO + PLANE_WORDS) * 4)   // 144,384 B

__launch_bounds__(256, 1)
__global__ void edge_kernel(const float* __restrict__ frac_diff,
                            const int*   __restrict__ ei,
                            const int*   __restrict__ e2g,
                            const float* __restrict__ e_w1,
                            const float* __restrict__ e_w2,
                            const float* __restrict__ e_b2)
{
    uint32_t* smw = (uint32_t*)dyn_smem;
    int*   srcs = (int*)(smw + O_SRC);
    int*   dsts = (int*)(smw + O_DST);
    int*   gs   = (int*)(smw + O_GS);
    float* fds  = (float*)(smw + O_FDS);
    float* b2s  = (float*)(smw + O_B2);
    float* w1ds = (float*)(smw + O_W1D);
    uint32_t* AHI = smw + O_AHI;
    uint32_t* ALO = smw + O_ALO;
    uint32_t* BHI = smw + O_BHI;
    uint32_t* BLO = smw + O_BLO;

    const int tid  = threadIdx.x;
    const int wid  = tid >> 5;
    const int lane = tid & 31;
    const int gid  = lane >> 2;     // 0..7
    const int tig  = lane & 3;      // 0..3

    // one-time: constants + B = W2^T hi/lo planes
    for (int i = tid; i < 384; i += 256) w1ds[i] = e_w1[262 * 128 + i];
    if (tid < 128) b2s[tid] = e_b2[tid];
    for (int idx = tid; idx < 8192; idx += 256) {
        int n = idx >> 6, p = idx & 63, k0 = p << 1;
        float v0 = e_w2[k0 * 128 + n];
        float v1 = e_w2[(k0 + 1) * 128 + n];
        uint32_t lo, hi = split_pack(v0, v1, lo);
        BHI[n * PLANE_WSTRIDE + p] = hi;
        BLO[n * PLANE_WSTRIDE + p] = lo;
    }

    for (int tile = blockIdx.x; tile < EDGE_NTILES; tile += gridDim.x) {
        __syncthreads();   // prev tile fully consumed before smem reuse
        const int e0 = tile * TILE_M;
        if (tid < 128) {
            int e = e0 + tid;
            int s = ei[e];
            srcs[tid] = s;
            dsts[tid] = ei[Ee + e];
            gs[tid]   = e2g[e];
            atomicAdd(&g_cnt[s], 1);
        }
        for (int i = tid; i < 384; i += 256) fds[i] = frac_diff[e0 * 3 + i];
        __syncthreads();

        // Phase A: e1 tile -> silu -> bf16 hi/lo planes (row-major padded)
#pragma unroll 4
        for (int idx = tid; idx < 8192; idx += 256) {
            int m = idx >> 6, p = idx & 63, c0 = p << 1;
            const float2 pa = *(const float2*)(g_Pa + srcs[m] * 128 + c0);
            const float2 pb = *(const float2*)(g_Pb + dsts[m] * 128 + c0);
            const float2 qb = *(const float2*)(g_Qb + gs[m] * 128 + c0);
            float f0 = fds[m * 3], f1 = fds[m * 3 + 1], f2 = fds[m * 3 + 2];
            float v0 = pa.x + pb.x + qb.x
                     + f0 * w1ds[c0] + f1 * w1ds[128 + c0] + f2 * w1ds[256 + c0];
            float v1 = pa.y + pb.y + qb.y
                     + f0 * w1ds[c0 + 1] + f1 * w1ds[129 + c0] + f2 * w1ds[257 + c0];
            v0 = silu_f(v0);
            v1 = silu_f(v1);
            uint32_t lo, hi = split_pack(v0, v1, lo);
            AHI[m * PLANE_WSTRIDE + p] = hi;
            ALO[m * PLANE_WSTRIDE + p] = lo;
        }
        __syncthreads();

        // MMA phase: warp wid handles rows [wid*16, wid*16+16), all 128 cols.
        float acc[16][4];
#pragma unroll
        for (int nf = 0; nf < 16; nf++)
#pragma unroll
            for (int j = 0; j < 4; j++) acc[nf][j] = 0.0f;

        const int ar0 = (wid * 16 + gid) * PLANE_WSTRIDE;
        const int ar1 = (wid * 16 + gid + 8) * PLANE_WSTRIDE;
#pragma unroll
        for (int ks = 0; ks < 8; ks++) {
            const int kw = ks * 8 + tig;
            uint32_t ah[4], al[4];
            ah[0] = AHI[ar0 + kw];     ah[1] = AHI[ar1 + kw];
            ah[2] = AHI[ar0 + kw + 4]; ah[3] = AHI[ar1 + kw + 4];
            al[0] = ALO[ar0 + kw];     al[1] = ALO[ar1 + kw];
            al[2] = ALO[ar0 + kw + 4]; al[3] = ALO[ar1 + kw + 4];
#pragma unroll
            for (int nf = 0; nf < 16; nf++) {
                const int nr = (nf * 8 + gid) * PLANE_WSTRIDE;
                uint32_t bh[2], bl[2];
                bh[0] = BHI[nr + kw]; bh[1] = BHI[nr + kw + 4];
                bl[0] = BLO[nr + kw]; bl[1] = BLO[nr + kw + 4];
                mma16816(acc[nf], ah, bh);
                mma16816(acc[nf], al, bh);
                mma16816(acc[nf], ah, bl);
            }
        }

        // Epilogue: bias + silu + vectorized reduction into g_agg[src]
        const int m1 = wid * 16 + gid;
        const int m2 = m1 + 8;
        float* agg1 = g_agg + srcs[m1] * 128;
        float* agg2 = g_agg + srcs[m2] * 128;
#pragma unroll
        for (int nf = 0; nf < 16; nf++) {
            const int col = nf * 8 + tig * 2;
            float b0 = b2s[col], b1 = b2s[col + 1];
            red_add_v2(agg1 + col, silu_f(acc[nf][0] + b0), silu_f(acc[nf][1] + b1));
            red_add_v2(agg2 + col, silu_f(acc[nf][2] + b0), silu_f(acc[nf][3] + b1));
        }
    }
}

// ---------------------------------------------------------------------------
// Kernel 4: node model + residual. 64 rows/block, 4x8 acc per thread.
// ---------------------------------------------------------------------------
#define XS_STRIDE 260
#define H1_STRIDE 132
#define NODE_ROWS 64
#define NODE_SMEM_FLOATS (NODE_ROWS * XS_STRIDE + NODE_ROWS * H1_STRIDE + 32 * 128 + 128 + 128 + NODE_ROWS)
#define NODE_SMEM_BYTES  (NODE_SMEM_FLOATS * 4)

__launch_bounds__(256, 1)
__global__ void node_out_kernel(const float* __restrict__ nf,
                                const float* __restrict__ n_w1,
                                const float* __restrict__ n_b1,
                                const float* __restrict__ n_w2,
                                const float* __restrict__ n_b2,
                                float* __restrict__ out)
{
    float* sm = (float*)dyn_smem;
    float* xs   = sm;                                   // 64 x 260
    float* h1s  = sm + NODE_ROWS * XS_STRIDE;           // 64 x 132
    float* wks  = h1s + NODE_ROWS * H1_STRIDE;          // 32 x 128
    float* b1s  = wks + 32 * 128;                       // 128
    float* b2s  = b1s + 128;                            // 128
    float* cinv = b2s + 128;                            // 64

    const int tid  = threadIdx.x;
    const int row0 = blockIdx.x * NODE_ROWS;

    if (tid < 128) { b1s[tid] = n_b1[tid]; b2s[tid] = n_b2[tid]; }
    if (tid < NODE_ROWS) {
        int row = row0 + tid;
        cinv[tid] = (row < Nn) ? 1.0f / fmaxf((float)g_cnt[row], 1.0f) : 0.0f;
    }
    __syncthreads();

    for (int idx = tid; idx < NODE_ROWS * 256; idx += 256) {
        int r = idx >> 8, c = idx & 255;
        int row = row0 + r;
        float v = 0.0f;
        if (row < Nn)
            v = (c < 128) ? nf[row * 128 + c]
                          : g_agg[row * 128 + (c - 128)] * cinv[r];
        xs[r * XS_STRIDE + c] = v;
    }

    const int ty = tid >> 4;   // 0..15 -> rows ty*4 .. +3
    const int tx = tid & 15;   // cols tx*8..+7

    // GEMM1: [64,256] @ [256,128]
    float acc[4][8];
#pragma unroll
    for (int i = 0; i < 4; i++)
#pragma unroll
        for (int j = 0; j < 8; j++) acc[i][j] = 0.0f;

    for (int kt = 0; kt < 256; kt += 32) {
        __syncthreads();
        for (int idx = tid; idx < 32 * 128; idx += 256) {
            int kl = idx >> 7, c = idx & 127;
            wks[idx] = n_w1[(kt + kl) * 128 + c];
        }
        __syncthreads();
#pragma unroll
        for (int kl = 0; kl < 32; kl++) {
            float a0 = xs[(ty * 4 + 0) * XS_STRIDE + kt + kl];
            float a1 = xs[(ty * 4 + 1) * XS_STRIDE + kt + kl];
            float a2 = xs[(ty * 4 + 2) * XS_STRIDE + kt + kl];
            float a3 = xs[(ty * 4 + 3) * XS_STRIDE + kt + kl];
            const float4 bA = *(const float4*)&wks[kl * 128 + tx * 8];
            const float4 bB = *(const float4*)&wks[kl * 128 + tx * 8 + 4];
            float bb[8] = {bA.x, bA.y, bA.z, bA.w, bB.x, bB.y, bB.z, bB.w};
#pragma unroll
            for (int j = 0; j < 8; j++) {
                acc[0][j] += a0 * bb[j];
                acc[1][j] += a1 * bb[j];
                acc[2][j] += a2 * bb[j];
                acc[3][j] += a3 * bb[j];
            }
        }
    }
    __syncthreads();
#pragma unroll
    for (int i = 0; i < 4; i++)
#pragma unroll
        for (int j = 0; j < 8; j++) {
            int c = tx * 8 + j;
            h1s[(ty * 4 + i) * H1_STRIDE + c] = silu_f(acc[i][j] + b1s[c]);
        }
    __syncthreads();

    // GEMM2: [64,128] @ [128,128]
    float acc2[4][8];
#pragma unroll
    for (int i = 0; i < 4; i++)
#pragma unroll
        for (int j = 0; j < 8; j++) acc2[i][j] = 0.0f;

    for (int kt = 0; kt < 128; kt += 32) {
        __syncthreads();
        for (int idx = tid; idx < 32 * 128; idx += 256) {
            int kl = idx >> 7, c = idx & 127;
            wks[idx] = n_w2[(kt + kl) * 128 + c];
        }
        __syncthreads();
#pragma unroll
        for (int kl = 0; kl < 32; kl++) {
            float a0 = h1s[(ty * 4 + 0) * H1_STRIDE + kt + kl];
            float a1 = h1s[(ty * 4 + 1) * H1_STRIDE + kt + kl];
            float a2 = h1s[(ty * 4 + 2) * H1_STRIDE + kt + kl];
            float a3 = h1s[(ty * 4 + 3) * H1_STRIDE + kt + kl];
            const float4 bA = *(const float4*)&wks[kl * 128 + tx * 8];
            const float4 bB = *(const float4*)&wks[kl * 128 + tx * 8 + 4];
            float bb[8] = {bA.x, bA.y, bA.z, bA.w, bB.x, bB.y, bB.z, bB.w};
#pragma unroll
            for (int j = 0; j < 8; j++) {
                acc2[0][j] += a0 * bb[j];
                acc2[1][j] += a1 * bb[j];
                acc2[2][j] += a2 * bb[j];
                acc2[3][j] += a3 * bb[j];
            }
        }
    }

#pragma unroll
    for (int i = 0; i < 4; i++) {
        int row = row0 + ty * 4 + i;
        if (row >= Nn) continue;
#pragma unroll
        for (int j = 0; j < 8; j++) {
            int c = tx * 8 + j;
            out[row * 128 + c] = nf[row * 128 + c] + silu_f(acc2[i][j] + b2s[c]);
        }
    }
}

// ---------------------------------------------------------------------------
extern "C" void kernel_launch(void* const* d_in, const int* in_sizes, int n_in,
                              void* d_out, int out_size)
{
    (void)in_sizes; (void)n_in; (void)out_size;
    const float* nf   = (const float*)d_in[0];
    const float* lat  = (const float*)d_in[2];
    const float* fd   = (const float*)d_in[3];
    const int*   ei   = (const int*)d_in[4];
    const int*   e2g  = (const int*)d_in[5];
    const float* e_w1 = (const float*)d_in[6];
    const float* e_b1 = (const float*)d_in[7];
    const float* e_w2 = (const float*)d_in[8];
    const float* e_b2 = (const float*)d_in[9];
    const float* n_w1 = (const float*)d_in[10];
    const float* n_b1 = (const float*)d_in[11];
    const float* n_w2 = (const float*)d_in[12];
    const float* n_b2 = (const float*)d_in[13];
    float* out = (float*)d_out;

    cudaFuncSetAttribute(edge_kernel,
                         cudaFuncAttributeMaxDynamicSharedMemorySize,
                         EDGE_SMEM_BYTES);
    cudaFuncSetAttribute(node_out_kernel,
                         cudaFuncAttributeMaxDynamicSharedMemorySize,
                         NODE_SMEM_BYTES);

    prep_node_kernel<<<(Nn + 31) / 32, 256>>>(nf, e_w1);
    prep_graph_kernel<<<Gg, 128>>>(lat, e_w1, e_b1);
    edge_kernel<<<148, 256, EDGE_SMEM_BYTES>>>(fd, ei, e2g, e_w1, e_w2, e_b2);
    node_out_kernel<<<(Nn + NODE_ROWS - 1) / NODE_ROWS, 256, NODE_SMEM_BYTES>>>(
        nf, n_w1, n_b1, n_w2, n_b2, out);
}

// round 5
// speedup vs baseline: 2.3446x; 1.9058x over previous
#include <cuda_runtime.h>
#include <cuda_bf16.h>
#include <cstdint>

#define Nn 50000
#define Ee 800000
#define Gg 2048
#define Hh 128

extern __shared__ char dyn_smem[];

// ---------------- device scratch ----------
__device__ float g_Pa[Nn * Hh];    // nf @ e_w1[0:128]
__device__ float g_Pb[Nn * Hh];    // nf @ e_w1[128:256]
__device__ float g_Pc[Nn * Hh];    // nf @ n_w1[0:128] + n_b1
__device__ float g_Qb[Gg * Hh];    // lat @ e_w1[256:262] + e_b1
__device__ float g_agg[Nn * Hh];   // scatter-sum accumulator
__device__ int   g_cnt[Nn];        // per-node edge count

__device__ __forceinline__ float silu_f(float x) {
    return x / (1.0f + __expf(-x));
}

// bf16 hi/lo split of a pair -> packed bf16x2 (hi returned, lo via ref)
__device__ __forceinline__ uint32_t split_pack(float v0, float v1, uint32_t& lo) {
    __nv_bfloat16 h0 = __float2bfloat16_rn(v0);
    __nv_bfloat16 h1 = __float2bfloat16_rn(v1);
    float r0 = v0 - __bfloat162float(h0);
    float r1 = v1 - __bfloat162float(h1);
    __nv_bfloat16 l0 = __float2bfloat16_rn(r0);
    __nv_bfloat16 l1 = __float2bfloat16_rn(r1);
    lo = (uint32_t)__bfloat16_as_ushort(l0) | ((uint32_t)__bfloat16_as_ushort(l1) << 16);
    return (uint32_t)__bfloat16_as_ushort(h0) | ((uint32_t)__bfloat16_as_ushort(h1) << 16);
}

// warp-level bf16 MMA, fp32 accum
__device__ __forceinline__ void mma16816(float* d, const uint32_t* a, const uint32_t* b) {
    asm volatile(
        "mma.sync.aligned.m16n8k16.row.col.f32.bf16.bf16.f32 "
        "{%0,%1,%2,%3}, {%4,%5,%6,%7}, {%8,%9}, {%0,%1,%2,%3};"
        : "+f"(d[0]), "+f"(d[1]), "+f"(d[2]), "+f"(d[3])
        : "r"(a[0]), "r"(a[1]), "r"(a[2]), "r"(a[3]), "r"(b[0]), "r"(b[1]));
}

__device__ __forceinline__ void red_add_v2(float* p, float a, float b) {
    asm volatile("red.global.add.v2.f32 [%0], {%1, %2};"
                 :: "l"(p), "f"(a), "f"(b) : "memory");
}

#define PWS 68   // plane word-stride per row (128 k = 64 pair-words + 4 pad)

// 3-chain hi/lo mma: acc += A(hi+lo) @ B(hi+lo) to ~fp32 accuracy
__device__ __forceinline__ void mma3(float* acc, const uint32_t* ah, const uint32_t* al,
                                     const uint32_t* bh, const uint32_t* bl) {
    mma16816(acc, ah, bh);
    mma16816(acc, al, bh);
    mma16816(acc, ah, bl);
}

// load A fragment (hi+lo) for row base ar0 (word offsets), k-word kw
__device__ __forceinline__ void load_afrag(uint32_t* ah, uint32_t* al,
                                           const uint32_t* AHI, const uint32_t* ALO,
                                           int ar0, int ar1, int kw) {
    ah[0] = AHI[ar0 + kw];     ah[1] = AHI[ar1 + kw];
    ah[2] = AHI[ar0 + kw + 4]; ah[3] = AHI[ar1 + kw + 4];
    al[0] = ALO[ar0 + kw];     al[1] = ALO[ar1 + kw];
    al[2] = ALO[ar0 + kw + 4]; al[3] = ALO[ar1 + kw + 4];
}

// ---------------------------------------------------------------------------
// Kernel 1 (mma): Pa/Pb/Pc precompute + zero agg/cnt. 128 rows per block.
//   Pa = nf@e_w1[0:128], Pb = nf@e_w1[128:256], Pc = nf@n_w1[0:128] + n_b1
// 512 threads; A planes resident per tile; B planes reloaded per output block.
// ---------------------------------------------------------------------------
#define P_BHI 0
#define P_BLO 8704
#define P_AHI 17408
#define P_ALO 26112
#define P_NB1 34816
#define PREP_SMEM_BYTES ((P_NB1 + 128) * 4)   // 139,776 B

__launch_bounds__(512, 1)
__global__ void prep_node_kernel(const float* __restrict__ nf,
                                 const float* __restrict__ e_w1,
                                 const float* __restrict__ n_w1,
                                 const float* __restrict__ n_b1)
{
    uint32_t* smw = (uint32_t*)dyn_smem;
    uint32_t* BHI = smw + P_BHI;
    uint32_t* BLO = smw + P_BLO;
    uint32_t* AHI = smw + P_AHI;
    uint32_t* ALO = smw + P_ALO;
    float*    NB1 = (float*)(smw + P_NB1);

    const int tid  = threadIdx.x;
    const int wid  = tid >> 5;
    const int lane = tid & 31;
    const int gid  = lane >> 2;
    const int tig  = lane & 3;
    const int row0 = blockIdx.x * 128;

    if (tid < 128) NB1[tid] = n_b1[tid];
    if (tid < 128 && row0 + tid < Nn) g_cnt[row0 + tid] = 0;

    // A split: nf rows -> hi/lo planes; zero g_agg rows alongside
    for (int idx = tid; idx < 8192; idx += 512) {
        int m = idx >> 6, p = idx & 63, c0 = p << 1;
        int row = row0 + m;
        float v0 = 0.0f, v1 = 0.0f;
        if (row < Nn) {
            const float2 v = *(const float2*)(nf + row * 128 + c0);
            v0 = v.x; v1 = v.y;
            *(float2*)(g_agg + row * 128 + c0) = make_float2(0.0f, 0.0f);
        }
        uint32_t lo, hi = split_pack(v0, v1, lo);
        AHI[m * PWS + p] = hi;
        ALO[m * PWS + p] = lo;
    }

    const int rg  = wid >> 1;      // row-group 0..7
    const int nfh = wid & 1;       // nf half
    const int ar0 = (rg * 16 + gid) * PWS;
    const int ar1 = ar0 + 8 * PWS;
    const int m1  = rg * 16 + gid;
    const int row1 = row0 + m1, row2 = row1 + 8;

    for (int blk = 0; blk < 3; blk++) {
        __syncthreads();   // prev mma reads done before B overwrite
        const float* bsrc = (blk == 0) ? e_w1
                          : (blk == 1) ? (e_w1 + 128 * 128)
                                       : n_w1;
        for (int idx = tid; idx < 8192; idx += 512) {
            int n = idx >> 6, p = idx & 63, k0 = p << 1;
            float v0 = bsrc[k0 * 128 + n];
            float v1 = bsrc[(k0 + 1) * 128 + n];
            uint32_t lo, hi = split_pack(v0, v1, lo);
            BHI[n * PWS + p] = hi;
            BLO[n * PWS + p] = lo;
        }
        __syncthreads();

        float acc[8][4];
#pragma unroll
        for (int j = 0; j < 8; j++)
#pragma unroll
            for (int q = 0; q < 4; q++) acc[j][q] = 0.0f;

#pragma unroll
        for (int ks = 0; ks < 8; ks++) {
            const int kw = ks * 8 + tig;
            uint32_t ah[4], al[4];
            load_afrag(ah, al, AHI, ALO, ar0, ar1, kw);
#pragma unroll
            for (int j = 0; j < 8; j++) {
                const int nr = ((nfh * 8 + j) * 8 + gid) * PWS;
                uint32_t bh[2] = {BHI[nr + kw], BHI[nr + kw + 4]};
                uint32_t bl[2] = {BLO[nr + kw], BLO[nr + kw + 4]};
                mma3(acc[j], ah, al, bh, bl);
            }
        }

        float* dst = (blk == 0) ? g_Pa : (blk == 1) ? g_Pb : g_Pc;
#pragma unroll
        for (int j = 0; j < 8; j++) {
            const int col = (nfh * 8 + j) * 8 + tig * 2;
            float b0 = 0.0f, b1 = 0.0f;
            if (blk == 2) { b0 = NB1[col]; b1 = NB1[col + 1]; }
            if (row1 < Nn)
                *(float2*)(dst + row1 * 128 + col) =
                    make_float2(acc[j][0] + b0, acc[j][1] + b1);
            if (row2 < Nn)
                *(float2*)(dst + row2 * 128 + col) =
                    make_float2(acc[j][2] + b0, acc[j][3] + b1);
        }
    }
}

// ---------------------------------------------------------------------------
// Kernel 2: per-graph lattice term + edge bias 1.
// ---------------------------------------------------------------------------
__global__ void prep_graph_kernel(const float* __restrict__ lat,
                                  const float* __restrict__ e_w1,
                                  const float* __restrict__ e_b1)
{
    const int g = blockIdx.x;
    const int c = threadIdx.x;
    float acc = e_b1[c];
#pragma unroll
    for (int k = 0; k < 6; k++)
        acc += lat[g * 6 + k] * e_w1[(256 + k) * 128 + c];
    g_Qb[g * 128 + c] = acc;
}

// ---------------------------------------------------------------------------
// Kernel 3: fused edge pipeline (mma.sync hi/lo). 256 edges/tile, 512 threads.
// ---------------------------------------------------------------------------
#define TILE_M 256
#define EDGE_NTILES (Ee / TILE_M)      // 3125

#define O_SRC   0
#define O_DST   256
#define O_GS    512
#define O_FDS   768
#define O_B2    1536
#define O_W1D   1664
#define O_AHI   2048
#define O_ALO   (O_AHI + 256 * PWS)
#define O_BHI   (O_ALO + 256 * PWS)
#define O_BLO   (O_BHI + 128 * PWS)
#define EDGE_SMEM_BYTES ((O_BLO + 128 * PWS) * 4)   // 217,088 B

__launch_bounds__(512, 1)
__global__ void edge_kernel(const float* __restrict__ frac_diff,
                            const int*   __restrict__ ei,
                            const int*   __restrict__ e2g,
                            const float* __restrict__ e_w1,
                            const float* __restrict__ e_w2,
                            const float* __restrict__ e_b2)
{
    uint32_t* smw = (uint32_t*)dyn_smem;
    int*   srcs = (int*)(smw + O_SRC);
    int*   dsts = (int*)(smw + O_DST);
    int*   gs   = (int*)(smw + O_GS);
    float* fds  = (float*)(smw + O_FDS);
    float* b2s  = (float*)(smw + O_B2);
    float* w1ds = (float*)(smw + O_W1D);
    uint32_t* AHI = smw + O_AHI;
    uint32_t* ALO = smw + O_ALO;
    uint32_t* BHI = smw + O_BHI;
    uint32_t* BLO = smw + O_BLO;

    const int tid  = threadIdx.x;
    const int wid  = tid >> 5;
    const int lane = tid & 31;
    const int gid  = lane >> 2;
    const int tig  = lane & 3;

    // one-time: constants + B = W2^T hi/lo planes
    for (int i = tid; i < 384; i += 512) w1ds[i] = e_w1[262 * 128 + i];
    if (tid < 128) b2s[tid] = e_b2[tid];
    for (int idx = tid; idx < 8192; idx += 512) {
        int n = idx >> 6, p = idx & 63, k0 = p << 1;
        float v0 = e_w2[k0 * 128 + n];
        float v1 = e_w2[(k0 + 1) * 128 + n];
        uint32_t lo, hi = split_pack(v0, v1, lo);
        BHI[n * PWS + p] = hi;
        BLO[n * PWS + p] = lo;
    }

    for (int tile = blockIdx.x; tile < EDGE_NTILES; tile += gridDim.x) {
        __syncthreads();
        const int e0 = tile * TILE_M;
        if (tid < 256) {
            int e = e0 + tid;
            int s = ei[e];
            srcs[tid] = s;
            dsts[tid] = ei[Ee + e];
            gs[tid]   = e2g[e];
            atomicAdd(&g_cnt[s], 1);
        }
        for (int i = tid; i < 768; i += 512) fds[i] = frac_diff[e0 * 3 + i];
        __syncthreads();

        // Phase A: e1 tile -> silu -> bf16 hi/lo planes
#pragma unroll 4
        for (int idx = tid; idx < 16384; idx += 512) {
            int m = idx >> 6, p = idx & 63, c0 = p << 1;
            const float2 pa = *(const float2*)(g_Pa + srcs[m] * 128 + c0);
            const float2 pb = *(const float2*)(g_Pb + dsts[m] * 128 + c0);
            const float2 qb = *(const float2*)(g_Qb + gs[m] * 128 + c0);
            float f0 = fds[m * 3], f1 = fds[m * 3 + 1], f2 = fds[m * 3 + 2];
            float v0 = pa.x + pb.x + qb.x
                     + f0 * w1ds[c0] + f1 * w1ds[128 + c0] + f2 * w1ds[256 + c0];
            float v1 = pa.y + pb.y + qb.y
                     + f0 * w1ds[c0 + 1] + f1 * w1ds[129 + c0] + f2 * w1ds[257 + c0];
            v0 = silu_f(v0);
            v1 = silu_f(v1);
            uint32_t lo, hi = split_pack(v0, v1, lo);
            AHI[m * PWS + p] = hi;
            ALO[m * PWS + p] = lo;
        }
        __syncthreads();

        // MMA: warp wid handles rows [wid*16, wid*16+16), all 128 cols
        float acc[16][4];
#pragma unroll
        for (int nf = 0; nf < 16; nf++)
#pragma unroll
            for (int j = 0; j < 4; j++) acc[nf][j] = 0.0f;

        const int ar0 = (wid * 16 + gid) * PWS;
        const int ar1 = ar0 + 8 * PWS;
#pragma unroll
        for (int ks = 0; ks < 8; ks++) {
            const int kw = ks * 8 + tig;
            uint32_t ah[4], al[4];
            load_afrag(ah, al, AHI, ALO, ar0, ar1, kw);
#pragma unroll
            for (int nf = 0; nf < 16; nf++) {
                const int nr = (nf * 8 + gid) * PWS;
                uint32_t bh[2] = {BHI[nr + kw], BHI[nr + kw + 4]};
                uint32_t bl[2] = {BLO[nr + kw], BLO[nr + kw + 4]};
                mma3(acc[nf], ah, al, bh, bl);
            }
        }

        // Epilogue: bias + silu + vectorized reduction into g_agg[src]
        const int m1 = wid * 16 + gid;
        const int m2 = m1 + 8;
        float* agg1 = g_agg + srcs[m1] * 128;
        float* agg2 = g_agg + srcs[m2] * 128;
#pragma unroll
        for (int nf = 0; nf < 16; nf++) {
            const int col = nf * 8 + tig * 2;
            float b0 = b2s[col], b1 = b2s[col + 1];
            red_add_v2(agg1 + col, silu_f(acc[nf][0] + b0), silu_f(acc[nf][1] + b1));
            red_add_v2(agg2 + col, silu_f(acc[nf][2] + b0), silu_f(acc[nf][3] + b1));
        }
    }
}

// ---------------------------------------------------------------------------
// Kernel 4 (mma): node model + residual, persistent. 128 rows/tile.
//   h1  = silu(Pc + (agg/cnt) @ n_w1[128:256])
//   out = nf + silu(h1 @ n_w2 + n_b2)
// ---------------------------------------------------------------------------
#define N_B1HI 0
#define N_B1LO 8704
#define N_B2HI 17408
#define N_B2LO 26112
#define N_AHI  34816
#define N_ALO  43520
#define N_NB2  52224
#define N_CINV 52352
#define NODE_SMEM_BYTES ((N_CINV + 128) * 4)   // 209,920 B
#define NODE_NTILES ((Nn + 127) / 128)          // 391

__launch_bounds__(512, 1)
__global__ void node_out_kernel(const float* __restrict__ nf,
                                const float* __restrict__ n_w1,
                                const float* __restrict__ n_w2,
                                const float* __restrict__ n_b2,
                                float* __restrict__ out)
{
    uint32_t* smw  = (uint32_t*)dyn_smem;
    uint32_t* B1HI = smw + N_B1HI;
    uint32_t* B1LO = smw + N_B1LO;
    uint32_t* B2HI = smw + N_B2HI;
    uint32_t* B2LO = smw + N_B2LO;
    uint32_t* AHI  = smw + N_AHI;
    uint32_t* ALO  = smw + N_ALO;
    float*    NB2  = (float*)(smw + N_NB2);
    float*    cinv = (float*)(smw + N_CINV);

    const int tid  = threadIdx.x;
    const int wid  = tid >> 5;
    const int lane = tid & 31;
    const int gid  = lane >> 2;
    const int tig  = lane & 3;

    // one-time B planes: B1[n][k]=n_w1[(128+k)*128+n], B2[n][k]=n_w2[k*128+n]
    if (tid < 128) NB2[tid] = n_b2[tid];
    for (int idx = tid; idx < 8192; idx += 512) {
        int n = idx >> 6, p = idx & 63, k0 = p << 1;
        float v0 = n_w1[(128 + k0) * 128 + n];
        float v1 = n_w1[(129 + k0) * 128 + n];
        uint32_t lo, hi = split_pack(v0, v1, lo);
        B1HI[n * PWS + p] = hi;
        B1LO[n * PWS + p] = lo;
        v0 = n_w2[k0 * 128 + n];
        v1 = n_w2[(k0 + 1) * 128 + n];
        hi = split_pack(v0, v1, lo);
        B2HI[n * PWS + p] = hi;
        B2LO[n * PWS + p] = lo;
    }

    const int rg  = wid >> 1;
    const int nfh = wid & 1;
    const int ar0 = (rg * 16 + gid) * PWS;
    const int ar1 = ar0 + 8 * PWS;
    const int m1  = rg * 16 + gid;
    const int m2  = m1 + 8;

    for (int tile = blockIdx.x; tile < NODE_NTILES; tile += gridDim.x) {
        const int row0 = tile * 128;
        __syncthreads();   // prev GEMM2 reads done before A reuse
        if (tid < 128) {
            int row = row0 + tid;
            cinv[tid] = (row < Nn) ? 1.0f / fmaxf((float)g_cnt[row], 1.0f) : 0.0f;
        }
        __syncthreads();

        // Phase A: agg/cnt -> hi/lo planes (coalesced, no gather)
        for (int idx = tid; idx < 8192; idx += 512) {
            int m = idx >> 6, p = idx & 63, c0 = p << 1;
            int row = row0 + m;
            float v0 = 0.0f, v1 = 0.0f;
            if (row < Nn) {
                const float2 v = *(const float2*)(g_agg + row * 128 + c0);
                v0 = v.x * cinv[m]; v1 = v.y * cinv[m];
            }
            uint32_t lo, hi = split_pack(v0, v1, lo);
            AHI[m * PWS + p] = hi;
            ALO[m * PWS + p] = lo;
        }
        __syncthreads();

        // GEMM1
        float acc[8][4];
#pragma unroll
        for (int j = 0; j < 8; j++)
#pragma unroll
            for (int q = 0; q < 4; q++) acc[j][q] = 0.0f;
#pragma unroll
        for (int ks = 0; ks < 8; ks++) {
            const int kw = ks * 8 + tig;
            uint32_t ah[4], al[4];
            load_afrag(ah, al, AHI, ALO, ar0, ar1, kw);
#pragma unroll
            for (int j = 0; j < 8; j++) {
                const int nr = ((nfh * 8 + j) * 8 + gid) * PWS;
                uint32_t bh[2] = {B1HI[nr + kw], B1HI[nr + kw + 4]};
                uint32_t bl[2] = {B1LO[nr + kw], B1LO[nr + kw + 4]};
                mma3(acc[j], ah, al, bh, bl);
            }
        }
        __syncthreads();   // all GEMM1 A-reads done before h1 overwrite

        // Epilogue1: h1 = silu(Pc + acc) -> back into A planes
        const int row1 = row0 + m1, row2 = row0 + m2;
#pragma unroll
        for (int j = 0; j < 8; j++) {
            const int col = (nfh * 8 + j) * 8 + tig * 2;
            const int p = col >> 1;
            float2 pc1 = make_float2(0.0f, 0.0f), pc2 = make_float2(0.0f, 0.0f);
            if (row1 < Nn) pc1 = *(const float2*)(g_Pc + row1 * 128 + col);
            if (row2 < Nn) pc2 = *(const float2*)(g_Pc + row2 * 128 + col);
            float h0 = silu_f(acc[j][0] + pc1.x);
            float h1v = silu_f(acc[j][1] + pc1.y);
            float h2 = silu_f(acc[j][2] + pc2.x);
            float h3 = silu_f(acc[j][3] + pc2.y);
            uint32_t lo, hi = split_pack(h0, h1v, lo);
            AHI[m1 * PWS + p] = hi; ALO[m1 * PWS + p] = lo;
            hi = split_pack(h2, h3, lo);
            AHI[m2 * PWS + p] = hi; ALO[m2 * PWS + p] = lo;
        }
        __syncthreads();

        // GEMM2
        float acc2[8][4];
#pragma unroll
        for (int j = 0; j < 8; j++)
#pragma unroll
            for (int q = 0; q < 4; q++) acc2[j][q] = 0.0f;
#pragma unroll
        for (int ks = 0; ks < 8; ks++) {
            const int kw = ks * 8 + tig;
            uint32_t ah[4], al[4];
            load_afrag(ah, al, AHI, ALO, ar0, ar1, kw);
#pragma unroll
            for (int j = 0; j < 8; j++) {
                const int nr = ((nfh * 8 + j) * 8 + gid) * PWS;
                uint32_t bh[2] = {B2HI[nr + kw], B2HI[nr + kw + 4]};
                uint32_t bl[2] = {B2LO[nr + kw], B2LO[nr + kw + 4]};
                mma3(acc2[j], ah, al, bh, bl);
            }
        }

        // Epilogue2: out = nf + silu(acc2 + b2)
#pragma unroll
        for (int j = 0; j < 8; j++) {
            const int col = (nfh * 8 + j) * 8 + tig * 2;
            float b0 = NB2[col], b1 = NB2[col + 1];
            if (row1 < Nn) {
                const float2 x = *(const float2*)(nf + row1 * 128 + col);
                *(float2*)(out + row1 * 128 + col) =
                    make_float2(x.x + silu_f(acc2[j][0] + b0),
                                x.y + silu_f(acc2[j][1] + b1));
            }
            if (row2 < Nn) {
                const float2 x = *(const float2*)(nf + row2 * 128 + col);
                *(float2*)(out + row2 * 128 + col) =
                    make_float2(x.x + silu_f(acc2[j][2] + b0),
                                x.y + silu_f(acc2[j][3] + b1));
            }
        }
    }
}

// ---------------------------------------------------------------------------
extern "C" void kernel_launch(void* const* d_in, const int* in_sizes, int n_in,
                              void* d_out, int out_size)
{
    (void)in_sizes; (void)n_in; (void)out_size;
    const float* nf   = (const float*)d_in[0];
    const float* lat  = (const float*)d_in[2];
    const float* fd   = (const float*)d_in[3];
    const int*   ei   = (const int*)d_in[4];
    const int*   e2g  = (const int*)d_in[5];
    const float* e_w1 = (const float*)d_in[6];
    const float* e_b1 = (const float*)d_in[7];
    const float* e_w2 = (const float*)d_in[8];
    const float* e_b2 = (const float*)d_in[9];
    const float* n_w1 = (const float*)d_in[10];
    const float* n_b1 = (const float*)d_in[11];
    const float* n_w2 = (const float*)d_in[12];
    const float* n_b2 = (const float*)d_in[13];
    float* out = (float*)d_out;

    cudaFuncSetAttribute(prep_node_kernel,
                         cudaFuncAttributeMaxDynamicSharedMemorySize,
                         PREP_SMEM_BYTES);
    cudaFuncSetAttribute(edge_kernel,
                         cudaFuncAttributeMaxDynamicSharedMemorySize,
                         EDGE_SMEM_BYTES);
    cudaFuncSetAttribute(node_out_kernel,
                         cudaFuncAttributeMaxDynamicSharedMemorySize,
                         NODE_SMEM_BYTES);

    prep_node_kernel<<<NODE_NTILES, 512, PREP_SMEM_BYTES>>>(nf, e_w1, n_w1, n_b1);
    prep_graph_kernel<<<Gg, 128>>>(lat, e_w1, e_b1);
    edge_kernel<<<148, 512, EDGE_SMEM_BYTES>>>(fd, ei, e2g, e_w1, e_w2, e_b2);
    node_out_kernel<<<148, 512, NODE_SMEM_BYTES>>>(nf, n_w1, n_w2, n_b2, out);
}